// round 6
// baseline (speedup 1.0000x reference)
#include <cuda_runtime.h>
#include <cuda_bf16.h>
#include <cstdint>
#include <math.h>

// ----------------------------------------------------------------------------
// B=128, T=2048, H=128
//   z = tanh(Hp @ Wh^T + Hd @ Wd^T); energy = z @ Wa + ba
//   alpha = softmax_T(energy * (1 + softplus(beta)*acc_w/max(acc_w)))
//   context = sum_t alpha * Hp
// Output: [context (B*H) | alpha (B*T)] fp32
//
// NOTE: harness ptxas targets sm_103 (non-'a') -> tcgen05 unavailable.
// Tensor path = mma.sync m16n8k16 bf16 with 3-term hi/lo split.
// ----------------------------------------------------------------------------

static constexpr int Bsz = 128, Tlen = 2048, Hdim = 128;
static constexpr int NTILES = Bsz * Tlen / 128;   // 2048 tiles of 128 tokens
static constexpr int GRID1  = 152;                // persistent CTAs (GB300 SMs)

__device__ float g_energy[Bsz * Tlen];

// ---------------------------- helpers ---------------------------------------
__device__ __forceinline__ uint32_t smem_u32(const void* p) {
    uint32_t a;
    asm("{ .reg .u64 t; cvta.to.shared.u64 t, %1; cvt.u32.u64 %0, t; }"
        : "=r"(a) : "l"(p));
    return a;
}

__device__ __forceinline__ void ldsm_x4(uint32_t* r, uint32_t addr) {
    asm volatile("ldmatrix.sync.aligned.m8n8.x4.shared.b16 {%0,%1,%2,%3}, [%4];"
                 : "=r"(r[0]), "=r"(r[1]), "=r"(r[2]), "=r"(r[3]) : "r"(addr));
}

__device__ __forceinline__ void mma16816(float* d, const uint32_t* a,
                                         uint32_t b0, uint32_t b1) {
    asm volatile("mma.sync.aligned.m16n8k16.row.col.f32.bf16.bf16.f32 "
                 "{%0,%1,%2,%3}, {%4,%5,%6,%7}, {%8,%9}, {%0,%1,%2,%3};"
                 : "+f"(d[0]), "+f"(d[1]), "+f"(d[2]), "+f"(d[3])
                 : "r"(a[0]), "r"(a[1]), "r"(a[2]), "r"(a[3]), "r"(b0), "r"(b1));
}

__device__ __forceinline__ float tanh_approx(float x) {
    float y;
    asm("tanh.approx.f32 %0, %1;" : "=f"(y) : "f"(x));
    return y;
}

// split two fp32 into packed bf16x2 hi and lo (residual)
__device__ __forceinline__ void split2(float x, float y, uint32_t& hi, uint32_t& lo) {
    __nv_bfloat16 hx = __float2bfloat16(x), hy = __float2bfloat16(y);
    float rx = x - __bfloat162float(hx);
    float ry = y - __bfloat162float(hy);
    __nv_bfloat16 lx = __float2bfloat16(rx), ly = __float2bfloat16(ry);
    hi = (uint32_t)__bfloat16_as_ushort(hx) | ((uint32_t)__bfloat16_as_ushort(hy) << 16);
    lo = (uint32_t)__bfloat16_as_ushort(lx) | ((uint32_t)__bfloat16_as_ushort(ly) << 16);
}

// ---------------------------- SMEM layout -----------------------------------
// All tiles 128 rows x 136 bf16 (pitch 272 B: 4-bank rotation per row ->
// conflict-free ldmatrix).
static constexpr int PITCH_B = 272;                  // bytes per row
static constexpr int TILE_B  = 128 * PITCH_B;        // 34816 B
static constexpr int SM_AH   = 0;                    // act hi
static constexpr int SM_AL   = SM_AH + TILE_B;       // act lo
static constexpr int SM_WHH  = SM_AL + TILE_B;       // Wh hi
static constexpr int SM_WHL  = SM_WHH + TILE_B;      // Wh lo
static constexpr int SM_WDH  = SM_WHL + TILE_B;      // Wd hi
static constexpr int SM_WDL  = SM_WDH + TILE_B;      // Wd lo
static constexpr int SM_WA   = SM_WDL + TILE_B;      // 128 fp32
static constexpr int SM_PART = SM_WA + 512;          // 2 x 128 fp32
static constexpr int SMEM1   = SM_PART + 1024;       // 210432 B

// convert a 128x128 fp32 row-major block into hi/lo bf16 padded tiles
__device__ __forceinline__ void convert_block(const float* __restrict__ src,
                                              char* smem, int dst_hi, int dst_lo,
                                              int tid) {
    const float4* g = (const float4*)src;
    #pragma unroll 4
    for (int i = tid; i < 4096; i += 256) {
        int row = i >> 5, c = i & 31;            // c = float4 index in row
        float4 v = g[i];
        uint32_t h0, l0, h1, l1;
        split2(v.x, v.y, h0, l0);
        split2(v.z, v.w, h1, l1);
        uint32_t off = (uint32_t)row * PITCH_B + (uint32_t)c * 8;
        *(uint2*)(smem + dst_hi + off) = make_uint2(h0, h1);
        *(uint2*)(smem + dst_lo + off) = make_uint2(l0, l1);
    }
}

// one GEMM term: D += A(tile at aBase) @ W(tile at wBase)^T
// warp grid 4(M) x 2(N): warp covers rows 32*wm..+31 (2 m-tiles),
// cols 64*wn..+63 (8 n-tiles). d[mt][nt][4].
__device__ __forceinline__ void mma_term(uint32_t aBase, uint32_t wBase,
                                         int lane, int wm, int wn,
                                         float d[2][8][4]) {
    uint32_t arow = (uint32_t)(wm * 32 + (lane & 15));
    uint32_t acol = (uint32_t)((lane >> 4) * 8);         // +0 / +8 (bf16 elems)
    uint32_t brow = (uint32_t)(wn * 64 + (lane & 7));
    uint32_t bcol = (uint32_t)((lane >> 3) * 8);         // 0/8/16/24
    #pragma unroll
    for (int k2 = 0; k2 < 4; k2++) {
        uint32_t k0 = (uint32_t)(k2 * 32);
        uint32_t a[2][2][4];
        #pragma unroll
        for (int mt = 0; mt < 2; mt++)
            #pragma unroll
            for (int ks = 0; ks < 2; ks++)
                ldsm_x4(a[mt][ks],
                        aBase + (arow + mt * 16) * PITCH_B
                              + (k0 + ks * 16 + acol) * 2);
        #pragma unroll
        for (int nt = 0; nt < 8; nt++) {
            uint32_t b[4];
            ldsm_x4(b, wBase + (brow + nt * 8) * PITCH_B + (k0 + bcol) * 2);
            mma16816(d[0][nt], a[0][0], b[0], b[1]);
            mma16816(d[0][nt], a[0][1], b[2], b[3]);
            mma16816(d[1][nt], a[1][0], b[0], b[1]);
            mma16816(d[1][nt], a[1][1], b[2], b[3]);
        }
    }
}

__global__ void __launch_bounds__(256, 1)
energy_kernel(const float* __restrict__ Hp, const float* __restrict__ Hd,
              const float* __restrict__ Wh, const float* __restrict__ Wd,
              const float* __restrict__ Wa, const float* __restrict__ ba_ptr) {
    extern __shared__ char smem[];
    uint32_t sb = smem_u32(smem);
    const int tid  = threadIdx.x;
    const int wid  = tid >> 5, lane = tid & 31;
    const int wm   = wid >> 1, wn = wid & 1;
    const int g    = lane >> 2, t = lane & 3;

    // --- one-time: convert weights fp32 -> bf16 hi/lo tiles ---
    convert_block(Wh, smem, SM_WHH, SM_WHL, tid);
    convert_block(Wd, smem, SM_WDH, SM_WDL, tid);
    if (tid < 128) ((float*)(smem + SM_WA))[tid] = Wa[tid];
    const float ba = ba_ptr[0];
    float* sPart = (float*)(smem + SM_PART);
    const float* sWa = (const float*)(smem + SM_WA);

    for (int tile = blockIdx.x; tile < NTILES; tile += gridDim.x) {
        float d[2][8][4];
        #pragma unroll
        for (int mt = 0; mt < 2; mt++)
            #pragma unroll
            for (int nt = 0; nt < 8; nt++)
                #pragma unroll
                for (int j = 0; j < 4; j++) d[mt][nt][j] = 0.f;

        size_t base = (size_t)tile * 128 * 128;
        #pragma unroll
        for (int pass = 0; pass < 2; pass++) {
            __syncthreads();    // previous users of AH/AL (and part reads) done
            convert_block(pass ? (Hd + base) : (Hp + base), smem, SM_AH, SM_AL, tid);
            __syncthreads();
            uint32_t whi = sb + (pass ? SM_WDH : SM_WHH);
            uint32_t wlo = sb + (pass ? SM_WDL : SM_WHL);
            mma_term(sb + SM_AH, whi, lane, wm, wn, d);   // hi*hi
            mma_term(sb + SM_AL, whi, lane, wm, wn, d);   // lo*hi
            mma_term(sb + SM_AH, wlo, lane, wm, wn, d);   // hi*lo
        }

        // --- epilogue: energy[token] = ba + sum_o Wa[o]*tanh(D[token][o]) ---
        float e[2][2] = {{0.f, 0.f}, {0.f, 0.f}};   // [mt][row-half]
        #pragma unroll
        for (int nt = 0; nt < 8; nt++) {
            int n = wn * 64 + nt * 8 + 2 * t;
            float wa0 = sWa[n], wa1 = sWa[n + 1];
            #pragma unroll
            for (int mt = 0; mt < 2; mt++) {
                e[mt][0] += wa0 * tanh_approx(d[mt][nt][0])
                          + wa1 * tanh_approx(d[mt][nt][1]);
                e[mt][1] += wa0 * tanh_approx(d[mt][nt][2])
                          + wa1 * tanh_approx(d[mt][nt][3]);
            }
        }
        // reduce over the 4 t-lanes (same g)
        #pragma unroll
        for (int mt = 0; mt < 2; mt++)
            #pragma unroll
            for (int r = 0; r < 2; r++) {
                e[mt][r] += __shfl_xor_sync(0xFFFFFFFFu, e[mt][r], 1);
                e[mt][r] += __shfl_xor_sync(0xFFFFFFFFu, e[mt][r], 2);
            }
        if (t == 0) {
            #pragma unroll
            for (int mt = 0; mt < 2; mt++) {
                int row = wm * 32 + mt * 16 + g;
                sPart[wn * 128 + row]     = e[mt][0];
                sPart[wn * 128 + row + 8] = e[mt][1];
            }
        }
        __syncthreads();
        if (tid < 128)
            g_energy[(size_t)tile * 128 + tid] = sPart[tid] + sPart[128 + tid] + ba;
    }
}

// ---------------------------- Kernel 2: softmax + context -------------------
__global__ void __launch_bounds__(256)
softmax_context_kernel(const float* __restrict__ Hp, const float* __restrict__ accw,
                       const float* __restrict__ beta_ptr, float* __restrict__ out) {
    __shared__ float s_e[2048];
    __shared__ float s_red[256];
    __shared__ float s_ctx[8 * 128];
    int b = blockIdx.x, tid = threadIdx.x;
    const float* aw = accw + (size_t)b * Tlen;
    const float* en = g_energy + (size_t)b * Tlen;

    // 1) max(acc_w)
    float lm = -INFINITY;
    for (int t = tid; t < Tlen; t += 256) lm = fmaxf(lm, aw[t]);
    s_red[tid] = lm; __syncthreads();
    for (int s = 128; s > 0; s >>= 1) {
        if (tid < s) s_red[tid] = fmaxf(s_red[tid], s_red[tid + s]);
        __syncthreads();
    }
    float denom = fmaxf(s_red[0], 1e-6f);
    __syncthreads();

    float bet = beta_ptr[0];
    float bp = (bet > 20.f) ? bet : log1pf(expf(bet));   // softplus

    // 2) scaled energy + max
    lm = -INFINITY;
    for (int t = tid; t < Tlen; t += 256) {
        float e = en[t] * (1.f + bp * (aw[t] / denom));
        s_e[t] = e;
        lm = fmaxf(lm, e);
    }
    s_red[tid] = lm; __syncthreads();
    for (int s = 128; s > 0; s >>= 1) {
        if (tid < s) s_red[tid] = fmaxf(s_red[tid], s_red[tid + s]);
        __syncthreads();
    }
    float m = s_red[0];
    __syncthreads();

    // 3) exp + sum
    float ls = 0.f;
    for (int t = tid; t < Tlen; t += 256) {
        float ex = expf(s_e[t] - m);
        s_e[t] = ex;
        ls += ex;
    }
    s_red[tid] = ls; __syncthreads();
    for (int s = 128; s > 0; s >>= 1) {
        if (tid < s) s_red[tid] += s_red[tid + s];
        __syncthreads();
    }
    float inv = 1.f / s_red[0];
    __syncthreads();

    // 4) alpha out
    float* alpha_out = out + Bsz * Hdim + (size_t)b * Tlen;
    for (int t = tid; t < Tlen; t += 256) {
        float a = s_e[t] * inv;
        s_e[t] = a;
        alpha_out[t] = a;
    }
    __syncthreads();

    // 5) context[h] = sum_t alpha[t] * Hp[b,t,h]
    int gg = tid >> 5, lane = tid & 31;
    const float4* hp = (const float4*)(Hp + (size_t)b * Tlen * Hdim);
    float4 acc = {0.f, 0.f, 0.f, 0.f};
    #pragma unroll 4
    for (int t = gg; t < Tlen; t += 8) {
        float a = s_e[t];
        float4 v = hp[t * 32 + lane];
        acc.x += a * v.x; acc.y += a * v.y; acc.z += a * v.z; acc.w += a * v.w;
    }
    s_ctx[gg * 128 + lane * 4 + 0] = acc.x;
    s_ctx[gg * 128 + lane * 4 + 1] = acc.y;
    s_ctx[gg * 128 + lane * 4 + 2] = acc.z;
    s_ctx[gg * 128 + lane * 4 + 3] = acc.w;
    __syncthreads();
    if (tid < 128) {
        float c = 0.f;
        #pragma unroll
        for (int w = 0; w < 8; w++) c += s_ctx[w * 128 + tid];
        out[(size_t)b * Hdim + tid] = c;
    }
}

// ---------------------------- launcher --------------------------------------
extern "C" void kernel_launch(void* const* d_in, const int* in_sizes, int n_in,
                              void* d_out, int out_size) {
    (void)in_sizes; (void)n_in; (void)out_size;
    const float* Hp   = (const float*)d_in[0];
    const float* Hd   = (const float*)d_in[1];
    const float* accw = (const float*)d_in[2];
    const float* Wh   = (const float*)d_in[3];
    const float* Wd   = (const float*)d_in[4];
    const float* Wa   = (const float*)d_in[5];
    const float* ba   = (const float*)d_in[6];
    const float* beta = (const float*)d_in[7];
    float* out = (float*)d_out;

    cudaFuncSetAttribute(energy_kernel, cudaFuncAttributeMaxDynamicSharedMemorySize, SMEM1);
    energy_kernel<<<GRID1, 256, SMEM1>>>(Hp, Hd, Wh, Wd, Wa, ba);
    softmax_context_kernel<<<Bsz, 256>>>(Hp, accw, beta, out);
}

// round 9
// speedup vs baseline: 1.7472x; 1.7472x over previous
#include <cuda_runtime.h>
#include <cuda_bf16.h>
#include <cuda_fp16.h>
#include <cstdint>
#include <math.h>

// ----------------------------------------------------------------------------
// B=128, T=2048, H=128
//   z = tanh(Hp @ Wh^T + Hd @ Wd^T); energy = z @ Wa + ba
//   alpha = softmax_T(energy * (1 + softplus(beta)*acc_w/max(acc_w)))
//   context = sum_t alpha * Hp
// Output: [context (B*H) | alpha (B*T)] fp32
//
// sm_103 (non-'a') ptxas: tcgen05 unavailable -> legacy mma.sync (HMMA).
// fp16 2-term split: pre = A_hi @ W_f16 + A_lo @ W_f16  (A = A_hi + A_lo exact
// to ~2^-22; only W's fp16 rounding (2^-11) is dropped -> ~1e-4 output error).
// ----------------------------------------------------------------------------

static constexpr int Bsz = 128, Tlen = 2048, Hdim = 128;
static constexpr int NTILES = Bsz * Tlen / 128;   // 2048 tiles of 128 tokens
static constexpr int GRID1  = 152;                // persistent CTAs (GB300 SMs)

__device__ float g_energy[Bsz * Tlen];
__device__ float g_ctx_part[Bsz * 8 * Hdim];      // context partials

// ---------------------------- helpers ---------------------------------------
__device__ __forceinline__ uint32_t smem_u32(const void* p) {
    uint32_t a;
    asm("{ .reg .u64 t; cvta.to.shared.u64 t, %1; cvt.u32.u64 %0, t; }"
        : "=r"(a) : "l"(p));
    return a;
}

__device__ __forceinline__ void ldsm_x4(uint32_t* r, uint32_t addr) {
    asm volatile("ldmatrix.sync.aligned.m8n8.x4.shared.b16 {%0,%1,%2,%3}, [%4];"
                 : "=r"(r[0]), "=r"(r[1]), "=r"(r[2]), "=r"(r[3]) : "r"(addr));
}

__device__ __forceinline__ void mma16816(float* d, const uint32_t* a,
                                         uint32_t b0, uint32_t b1) {
    asm volatile("mma.sync.aligned.m16n8k16.row.col.f32.f16.f16.f32 "
                 "{%0,%1,%2,%3}, {%4,%5,%6,%7}, {%8,%9}, {%0,%1,%2,%3};"
                 : "+f"(d[0]), "+f"(d[1]), "+f"(d[2]), "+f"(d[3])
                 : "r"(a[0]), "r"(a[1]), "r"(a[2]), "r"(a[3]), "r"(b0), "r"(b1));
}

__device__ __forceinline__ float tanh_approx(float x) {
    float y;
    asm("tanh.approx.f32 %0, %1;" : "=f"(y) : "f"(x));
    return y;
}

__device__ __forceinline__ void cp_async16(uint32_t saddr, const void* g) {
    asm volatile("cp.async.cg.shared.global [%0], [%1], 16;" :: "r"(saddr), "l"(g));
}
#define CP_COMMIT() asm volatile("cp.async.commit_group;" ::: "memory")
#define CP_WAIT0()  asm volatile("cp.async.wait_group 0;" ::: "memory")

// split two fp32 into packed fp16x2 hi and lo (residual)
__device__ __forceinline__ void split2h(float x, float y, uint32_t& hi, uint32_t& lo) {
    __half hx = __float2half_rn(x), hy = __float2half_rn(y);
    float rx = x - __half2float(hx);
    float ry = y - __half2float(hy);
    __half lx = __float2half_rn(rx), ly = __float2half_rn(ry);
    hi = (uint32_t)__half_as_ushort(hx) | ((uint32_t)__half_as_ushort(hy) << 16);
    lo = (uint32_t)__half_as_ushort(lx) | ((uint32_t)__half_as_ushort(ly) << 16);
}

// ---------------------------- SMEM layout -----------------------------------
// fp16 tiles: 128 rows x 136 halves (pitch 272 B -> 4-bank row rotation,
// conflict-free ldmatrix).
static constexpr int PITCH_B  = 272;
static constexpr int TILE_B   = 128 * PITCH_B;       // 34816 B
static constexpr int SM_AH    = 0;                   // act hi (fp16)
static constexpr int SM_AL    = SM_AH + TILE_B;      // act lo (fp16)
static constexpr int SM_WH    = SM_AL + TILE_B;      // Wh (fp16)
static constexpr int SM_WD    = SM_WH + TILE_B;      // Wd (fp16)
static constexpr int SM_STAGE = SM_WD + TILE_B;      // 139264: raw fp32 128x128
static constexpr int SM_WA    = SM_STAGE + 65536;    // 204800
static constexpr int SM_PART  = SM_WA + 512;         // 205312: 2x128 fp32
static constexpr int SMEM1    = SM_PART + 1024;      // 206336 B

// issue cp.async of one 128x128 fp32 block into the stage buffer
__device__ __forceinline__ void stage_load(uint32_t sb, const float* __restrict__ src,
                                           int tid) {
    #pragma unroll
    for (int k = 0; k < 16; k++) {
        int i = tid + 256 * k;
        cp_async16(sb + SM_STAGE + (uint32_t)i * 16, src + i * 4);
    }
    CP_COMMIT();
}

// convert stage (fp32) -> AH/AL fp16 hi/lo tiles
__device__ __forceinline__ void convert_stage(char* smem, int tid) {
    const float4* stg = (const float4*)(smem + SM_STAGE);
    #pragma unroll 4
    for (int k = 0; k < 16; k++) {
        int i = tid + 256 * k;
        float4 v = stg[i];
        int row = i >> 5, c = i & 31;
        uint32_t h0, l0, h1, l1;
        split2h(v.x, v.y, h0, l0);
        split2h(v.z, v.w, h1, l1);
        uint32_t off = (uint32_t)row * PITCH_B + (uint32_t)c * 8;
        *(uint2*)(smem + SM_AH + off) = make_uint2(h0, h1);
        *(uint2*)(smem + SM_AL + off) = make_uint2(l0, l1);
    }
}

// one GEMM term: D += A(tile at aBase) @ W(tile at wBase)^T
// warp grid 4(M) x 2(N): warp = rows 32*wm..+31 (2 m-tiles), cols 64*wn..+63.
__device__ __forceinline__ void mma_term(uint32_t aBase, uint32_t wBase,
                                         int lane, int wm, int wn,
                                         float d[2][8][4]) {
    uint32_t arow = (uint32_t)(wm * 32 + (lane & 15));
    uint32_t acol = (uint32_t)((lane >> 4) * 8);
    uint32_t brow = (uint32_t)(wn * 64 + (lane & 7));
    uint32_t bcol = (uint32_t)((lane >> 3) * 8);
    #pragma unroll
    for (int k2 = 0; k2 < 4; k2++) {
        uint32_t k0 = (uint32_t)(k2 * 32);
        uint32_t a[2][2][4];
        #pragma unroll
        for (int mt = 0; mt < 2; mt++)
            #pragma unroll
            for (int ks = 0; ks < 2; ks++)
                ldsm_x4(a[mt][ks],
                        aBase + (arow + mt * 16) * PITCH_B
                              + (k0 + ks * 16 + acol) * 2);
        #pragma unroll
        for (int nt = 0; nt < 8; nt++) {
            uint32_t b[4];
            ldsm_x4(b, wBase + (brow + nt * 8) * PITCH_B + (k0 + bcol) * 2);
            mma16816(d[0][nt], a[0][0], b[0], b[1]);
            mma16816(d[0][nt], a[0][1], b[2], b[3]);
            mma16816(d[1][nt], a[1][0], b[0], b[1]);
            mma16816(d[1][nt], a[1][1], b[2], b[3]);
        }
    }
}

__global__ void __launch_bounds__(256, 1)
energy_kernel(const float* __restrict__ Hp, const float* __restrict__ Hd,
              const float* __restrict__ Wh, const float* __restrict__ Wd,
              const float* __restrict__ Wa, const float* __restrict__ ba_ptr) {
    extern __shared__ char smem[];
    uint32_t sb = smem_u32(smem);
    const int tid = threadIdx.x;
    const int wid = tid >> 5, lane = tid & 31;
    const int wm  = wid >> 1, wn = wid & 1;
    const int g   = lane >> 2, t = lane & 3;

    // one-time: weights fp32 -> fp16 tiles
    for (int idx = tid; idx < 8192; idx += 256) {
        int o = idx >> 6, h = (idx & 63) * 2;
        uint32_t off = (uint32_t)o * PITCH_B + (uint32_t)h * 2;
        float2 a = *(const float2*)(Wh + o * 128 + h);
        float2 b = *(const float2*)(Wd + o * 128 + h);
        __half2 ah = __floats2half2_rn(a.x, a.y);
        __half2 bh = __floats2half2_rn(b.x, b.y);
        *(uint32_t*)(smem + SM_WH + off) = *(const uint32_t*)&ah;
        *(uint32_t*)(smem + SM_WD + off) = *(const uint32_t*)&bh;
    }
    if (tid < 128) ((float*)(smem + SM_WA))[tid] = Wa[tid];
    const float ba = ba_ptr[0];
    float* sPart = (float*)(smem + SM_PART);
    const float* sWa = (const float*)(smem + SM_WA);

    // preload first Hp tile
    if (blockIdx.x < NTILES)
        stage_load(sb, Hp + (size_t)blockIdx.x * 16384, tid);

    for (int tile = blockIdx.x; tile < NTILES; tile += GRID1) {
        size_t base = (size_t)tile * 16384;
        float d[2][8][4];
        #pragma unroll
        for (int mt = 0; mt < 2; mt++)
            #pragma unroll
            for (int nt = 0; nt < 8; nt++)
                #pragma unroll
                for (int j = 0; j < 4; j++) d[mt][nt][j] = 0.f;

        // ---- pass 1: Hp ----
        CP_WAIT0();
        __syncthreads();                 // stage ready, AH/AL free
        convert_stage(smem, tid);
        __syncthreads();                 // AH/AL ready, stage free
        stage_load(sb, Hd + base, tid);  // prefetch Hd under MMA
        mma_term(sb + SM_AH, sb + SM_WH, lane, wm, wn, d);
        mma_term(sb + SM_AL, sb + SM_WH, lane, wm, wn, d);

        // ---- pass 2: Hd ----
        CP_WAIT0();
        __syncthreads();                 // Hd staged, AH/AL reads done
        convert_stage(smem, tid);
        __syncthreads();
        if (tile + GRID1 < NTILES)       // prefetch next Hp under MMA
            stage_load(sb, Hp + base + (size_t)GRID1 * 16384, tid);
        mma_term(sb + SM_AH, sb + SM_WD, lane, wm, wn, d);
        mma_term(sb + SM_AL, sb + SM_WD, lane, wm, wn, d);

        // ---- epilogue: energy[token] = ba + sum_o Wa[o]*tanh(D[token][o]) ----
        float e[2][2] = {{0.f, 0.f}, {0.f, 0.f}};
        #pragma unroll
        for (int nt = 0; nt < 8; nt++) {
            int n = wn * 64 + nt * 8 + 2 * t;
            float wa0 = sWa[n], wa1 = sWa[n + 1];
            #pragma unroll
            for (int mt = 0; mt < 2; mt++) {
                e[mt][0] += wa0 * tanh_approx(d[mt][nt][0])
                          + wa1 * tanh_approx(d[mt][nt][1]);
                e[mt][1] += wa0 * tanh_approx(d[mt][nt][2])
                          + wa1 * tanh_approx(d[mt][nt][3]);
            }
        }
        #pragma unroll
        for (int mt = 0; mt < 2; mt++)
            #pragma unroll
            for (int r = 0; r < 2; r++) {
                e[mt][r] += __shfl_xor_sync(0xFFFFFFFFu, e[mt][r], 1);
                e[mt][r] += __shfl_xor_sync(0xFFFFFFFFu, e[mt][r], 2);
            }
        if (t == 0) {
            #pragma unroll
            for (int mt = 0; mt < 2; mt++) {
                int row = wm * 32 + mt * 16 + g;
                sPart[wn * 128 + row]     = e[mt][0];
                sPart[wn * 128 + row + 8] = e[mt][1];
            }
        }
        __syncthreads();
        if (tid < 128)
            g_energy[(size_t)tile * 128 + tid] = sPart[tid] + sPart[128 + tid] + ba;
    }
}

// ---------------------------- Kernel 2: softmax -> alpha --------------------
__global__ void __launch_bounds__(256)
softmax_kernel(const float* __restrict__ accw, const float* __restrict__ beta_ptr,
               float* __restrict__ out) {
    __shared__ float s_e[2048];
    __shared__ float s_red[256];
    int b = blockIdx.x, tid = threadIdx.x;
    const float* aw = accw + (size_t)b * Tlen;
    const float* en = g_energy + (size_t)b * Tlen;

    float lm = -INFINITY;
    for (int t = tid; t < Tlen; t += 256) lm = fmaxf(lm, aw[t]);
    s_red[tid] = lm; __syncthreads();
    for (int s = 128; s > 0; s >>= 1) {
        if (tid < s) s_red[tid] = fmaxf(s_red[tid], s_red[tid + s]);
        __syncthreads();
    }
    float denom = fmaxf(s_red[0], 1e-6f);
    __syncthreads();

    float bet = beta_ptr[0];
    float bp = (bet > 20.f) ? bet : log1pf(expf(bet));

    lm = -INFINITY;
    for (int t = tid; t < Tlen; t += 256) {
        float e = en[t] * (1.f + bp * (aw[t] / denom));
        s_e[t] = e;
        lm = fmaxf(lm, e);
    }
    s_red[tid] = lm; __syncthreads();
    for (int s = 128; s > 0; s >>= 1) {
        if (tid < s) s_red[tid] = fmaxf(s_red[tid], s_red[tid + s]);
        __syncthreads();
    }
    float m = s_red[0];
    __syncthreads();

    float ls = 0.f;
    for (int t = tid; t < Tlen; t += 256) {
        float ex = expf(s_e[t] - m);
        s_e[t] = ex;
        ls += ex;
    }
    s_red[tid] = ls; __syncthreads();
    for (int s = 128; s > 0; s >>= 1) {
        if (tid < s) s_red[tid] += s_red[tid + s];
        __syncthreads();
    }
    float inv = 1.f / s_red[0];
    __syncthreads();

    float* alpha_out = out + Bsz * Hdim + (size_t)b * Tlen;
    for (int t = tid; t < Tlen; t += 256)
        alpha_out[t] = s_e[t] * inv;
}

// -------------------- Kernel 3: context partials (1024 CTAs) ----------------
__global__ void __launch_bounds__(256)
context_partial_kernel(const float* __restrict__ Hp, const float* __restrict__ out) {
    __shared__ float s_a[256];
    __shared__ float s_ctx[8 * 128];
    int b = blockIdx.x >> 3, chunk = blockIdx.x & 7;
    int tid = threadIdx.x, w = tid >> 5, lane = tid & 31;

    const float* alpha = out + Bsz * Hdim + (size_t)b * Tlen + chunk * 256;
    s_a[tid] = alpha[tid];
    __syncthreads();

    const float4* hp = (const float4*)(Hp + ((size_t)b * Tlen + chunk * 256) * Hdim);
    float4 acc = {0.f, 0.f, 0.f, 0.f};
    #pragma unroll 4
    for (int t = w; t < 256; t += 8) {
        float a = s_a[t];
        float4 v = hp[t * 32 + lane];
        acc.x += a * v.x; acc.y += a * v.y; acc.z += a * v.z; acc.w += a * v.w;
    }
    s_ctx[w * 128 + lane * 4 + 0] = acc.x;
    s_ctx[w * 128 + lane * 4 + 1] = acc.y;
    s_ctx[w * 128 + lane * 4 + 2] = acc.z;
    s_ctx[w * 128 + lane * 4 + 3] = acc.w;
    __syncthreads();
    if (tid < 128) {
        float c = 0.f;
        #pragma unroll
        for (int ww = 0; ww < 8; ww++) c += s_ctx[ww * 128 + tid];
        g_ctx_part[(size_t)blockIdx.x * 128 + tid] = c;
    }
}

// -------------------- Kernel 4: reduce 8 partials per batch -----------------
__global__ void __launch_bounds__(128)
context_reduce_kernel(float* __restrict__ out) {
    int b = blockIdx.x, tid = threadIdx.x;
    float c = 0.f;
    #pragma unroll
    for (int k = 0; k < 8; k++)
        c += g_ctx_part[((size_t)b * 8 + k) * 128 + tid];
    out[(size_t)b * Hdim + tid] = c;
}

// ---------------------------- launcher --------------------------------------
extern "C" void kernel_launch(void* const* d_in, const int* in_sizes, int n_in,
                              void* d_out, int out_size) {
    (void)in_sizes; (void)n_in; (void)out_size;
    const float* Hp   = (const float*)d_in[0];
    const float* Hd   = (const float*)d_in[1];
    const float* accw = (const float*)d_in[2];
    const float* Wh   = (const float*)d_in[3];
    const float* Wd   = (const float*)d_in[4];
    const float* Wa   = (const float*)d_in[5];
    const float* ba   = (const float*)d_in[6];
    const float* beta = (const float*)d_in[7];
    float* out = (float*)d_out;

    cudaFuncSetAttribute(energy_kernel, cudaFuncAttributeMaxDynamicSharedMemorySize, SMEM1);
    energy_kernel<<<GRID1, 256, SMEM1>>>(Hp, Hd, Wh, Wd, Wa, ba);
    softmax_kernel<<<Bsz, 256>>>(accw, beta, out);
    context_partial_kernel<<<Bsz * 8, 256>>>(Hp, out);
    context_reduce_kernel<<<Bsz, 128>>>(out);
}

// round 11
// speedup vs baseline: 2.7679x; 1.5842x over previous
#include <cuda_runtime.h>
#include <cuda_bf16.h>
#include <cuda_fp16.h>
#include <cstdint>
#include <math.h>

// ----------------------------------------------------------------------------
// B=128, T=2048, H=128
//   z = tanh(Hp @ Wh^T + Hd @ Wd^T); energy = z @ Wa + ba
//   alpha = softmax_T(energy * (1 + softplus(beta)*acc_w/max(acc_w)))
//   context = sum_t alpha * Hp
// Output: [context (B*H) | alpha (B*T)] fp32
//
// sm_103 (non-'a') ptxas: tcgen05 unavailable -> legacy mma.sync (HMMA).
// Single-term fp16 MMA: pre = A_f16 @ W_f16, fp32 accumulate.
// Incoherent 2^-11 rounding on A and W -> ~3e-4 final rel err (budget 1e-3).
// ----------------------------------------------------------------------------

static constexpr int Bsz = 128, Tlen = 2048, Hdim = 128;
static constexpr int NTILES = Bsz * Tlen / 128;   // 2048 tiles of 128 tokens
static constexpr int GRID1  = 152;                // persistent CTAs (GB300 SMs)

__device__ float g_energy[Bsz * Tlen];
__device__ float g_ctx_part[Bsz * 8 * Hdim];      // context partials

// ---------------------------- helpers ---------------------------------------
__device__ __forceinline__ uint32_t smem_u32(const void* p) {
    uint32_t a;
    asm("{ .reg .u64 t; cvta.to.shared.u64 t, %1; cvt.u32.u64 %0, t; }"
        : "=r"(a) : "l"(p));
    return a;
}

__device__ __forceinline__ void ldsm_x4(uint32_t* r, uint32_t addr) {
    asm volatile("ldmatrix.sync.aligned.m8n8.x4.shared.b16 {%0,%1,%2,%3}, [%4];"
                 : "=r"(r[0]), "=r"(r[1]), "=r"(r[2]), "=r"(r[3]) : "r"(addr));
}

__device__ __forceinline__ void mma16816(float* d, const uint32_t* a,
                                         uint32_t b0, uint32_t b1) {
    asm volatile("mma.sync.aligned.m16n8k16.row.col.f32.f16.f16.f32 "
                 "{%0,%1,%2,%3}, {%4,%5,%6,%7}, {%8,%9}, {%0,%1,%2,%3};"
                 : "+f"(d[0]), "+f"(d[1]), "+f"(d[2]), "+f"(d[3])
                 : "r"(a[0]), "r"(a[1]), "r"(a[2]), "r"(a[3]), "r"(b0), "r"(b1));
}

__device__ __forceinline__ float tanh_approx(float x) {
    float y;
    asm("tanh.approx.f32 %0, %1;" : "=f"(y) : "f"(x));
    return y;
}

__device__ __forceinline__ void cp_async16(uint32_t saddr, const void* g) {
    asm volatile("cp.async.cg.shared.global [%0], [%1], 16;" :: "r"(saddr), "l"(g));
}
#define CP_COMMIT() asm volatile("cp.async.commit_group;" ::: "memory")
#define CP_WAIT0()  asm volatile("cp.async.wait_group 0;" ::: "memory")

// ---------------------------- SMEM layout -----------------------------------
// fp16 tiles: 128 rows x 136 halves (pitch 272 B -> 4-bank row rotation,
// conflict-free ldmatrix).
static constexpr int PITCH_B  = 272;
static constexpr int TILE_B   = 128 * PITCH_B;       // 34816 B
static constexpr int SM_AH    = 0;                   // act (fp16)
static constexpr int SM_WH    = SM_AH + TILE_B;      // Wh (fp16)
static constexpr int SM_WD    = SM_WH + TILE_B;      // Wd (fp16)
static constexpr int SM_STAGE = SM_WD + TILE_B;      // raw fp32 128x128
static constexpr int SM_WA    = SM_STAGE + 65536;
static constexpr int SM_PART  = SM_WA + 512;         // 2x128 fp32
static constexpr int SMEM1    = SM_PART + 1024;      // 171520 B

// issue cp.async of one 128x128 fp32 block into the stage buffer
__device__ __forceinline__ void stage_load(uint32_t sb, const float* __restrict__ src,
                                           int tid) {
    #pragma unroll
    for (int k = 0; k < 16; k++) {
        int i = tid + 256 * k;
        cp_async16(sb + SM_STAGE + (uint32_t)i * 16, src + i * 4);
    }
    CP_COMMIT();
}

// convert stage (fp32) -> fp16 tile at SM_AH
__device__ __forceinline__ void convert_stage(char* smem, int tid) {
    const float4* stg = (const float4*)(smem + SM_STAGE);
    #pragma unroll 4
    for (int k = 0; k < 16; k++) {
        int i = tid + 256 * k;
        float4 v = stg[i];
        int row = i >> 5, c = i & 31;
        __half2 h0 = __floats2half2_rn(v.x, v.y);
        __half2 h1 = __floats2half2_rn(v.z, v.w);
        uint32_t off = (uint32_t)row * PITCH_B + (uint32_t)c * 8;
        *(uint2*)(smem + SM_AH + off) =
            make_uint2(*(const uint32_t*)&h0, *(const uint32_t*)&h1);
    }
}

// one GEMM term: D += A(tile at aBase) @ W(tile at wBase)^T
// warp grid 4(M) x 2(N): warp = rows 32*wm..+31 (2 m-tiles), cols 64*wn..+63.
__device__ __forceinline__ void mma_term(uint32_t aBase, uint32_t wBase,
                                         int lane, int wm, int wn,
                                         float d[2][8][4]) {
    uint32_t arow = (uint32_t)(wm * 32 + (lane & 15));
    uint32_t acol = (uint32_t)((lane >> 4) * 8);
    uint32_t brow = (uint32_t)(wn * 64 + (lane & 7));
    uint32_t bcol = (uint32_t)((lane >> 3) * 8);
    #pragma unroll
    for (int k2 = 0; k2 < 4; k2++) {
        uint32_t k0 = (uint32_t)(k2 * 32);
        uint32_t a[2][2][4];
        #pragma unroll
        for (int mt = 0; mt < 2; mt++)
            #pragma unroll
            for (int ks = 0; ks < 2; ks++)
                ldsm_x4(a[mt][ks],
                        aBase + (arow + mt * 16) * PITCH_B
                              + (k0 + ks * 16 + acol) * 2);
        #pragma unroll
        for (int nt = 0; nt < 8; nt++) {
            uint32_t b[4];
            ldsm_x4(b, wBase + (brow + nt * 8) * PITCH_B + (k0 + bcol) * 2);
            mma16816(d[0][nt], a[0][0], b[0], b[1]);
            mma16816(d[0][nt], a[0][1], b[2], b[3]);
            mma16816(d[1][nt], a[1][0], b[0], b[1]);
            mma16816(d[1][nt], a[1][1], b[2], b[3]);
        }
    }
}

__global__ void __launch_bounds__(256, 1)
energy_kernel(const float* __restrict__ Hp, const float* __restrict__ Hd,
              const float* __restrict__ Wh, const float* __restrict__ Wd,
              const float* __restrict__ Wa, const float* __restrict__ ba_ptr) {
    extern __shared__ char smem[];
    uint32_t sb = smem_u32(smem);
    const int tid = threadIdx.x;
    const int wid = tid >> 5, lane = tid & 31;
    const int wm  = wid >> 1, wn = wid & 1;
    const int g   = lane >> 2, t = lane & 3;

    // one-time: weights fp32 -> fp16 tiles
    for (int idx = tid; idx < 8192; idx += 256) {
        int o = idx >> 6, h = (idx & 63) * 2;
        uint32_t off = (uint32_t)o * PITCH_B + (uint32_t)h * 2;
        float2 a = *(const float2*)(Wh + o * 128 + h);
        float2 b = *(const float2*)(Wd + o * 128 + h);
        __half2 ah = __floats2half2_rn(a.x, a.y);
        __half2 bh = __floats2half2_rn(b.x, b.y);
        *(uint32_t*)(smem + SM_WH + off) = *(const uint32_t*)&ah;
        *(uint32_t*)(smem + SM_WD + off) = *(const uint32_t*)&bh;
    }
    if (tid < 128) ((float*)(smem + SM_WA))[tid] = Wa[tid];
    const float ba = ba_ptr[0];
    float* sPart = (float*)(smem + SM_PART);
    const float* sWa = (const float*)(smem + SM_WA);

    // preload first Hp tile
    if (blockIdx.x < NTILES)
        stage_load(sb, Hp + (size_t)blockIdx.x * 16384, tid);

    for (int tile = blockIdx.x; tile < NTILES; tile += GRID1) {
        size_t base = (size_t)tile * 16384;
        float d[2][8][4];
        #pragma unroll
        for (int mt = 0; mt < 2; mt++)
            #pragma unroll
            for (int nt = 0; nt < 8; nt++)
                #pragma unroll
                for (int j = 0; j < 4; j++) d[mt][nt][j] = 0.f;

        // ---- pass 1: Hp ----
        CP_WAIT0();
        __syncthreads();                 // stage ready, AH free
        convert_stage(smem, tid);
        __syncthreads();                 // AH ready, stage free
        stage_load(sb, Hd + base, tid);  // prefetch Hd under MMA
        mma_term(sb + SM_AH, sb + SM_WH, lane, wm, wn, d);

        // ---- pass 2: Hd ----
        CP_WAIT0();
        __syncthreads();                 // Hd staged, AH reads done
        convert_stage(smem, tid);
        __syncthreads();
        if (tile + GRID1 < NTILES)       // prefetch next Hp under MMA
            stage_load(sb, Hp + base + (size_t)GRID1 * 16384, tid);
        mma_term(sb + SM_AH, sb + SM_WD, lane, wm, wn, d);

        // ---- epilogue: energy[token] = ba + sum_o Wa[o]*tanh(D[token][o]) ----
        float e[2][2] = {{0.f, 0.f}, {0.f, 0.f}};
        #pragma unroll
        for (int nt = 0; nt < 8; nt++) {
            int n = wn * 64 + nt * 8 + 2 * t;
            float wa0 = sWa[n], wa1 = sWa[n + 1];
            #pragma unroll
            for (int mt = 0; mt < 2; mt++) {
                e[mt][0] += wa0 * tanh_approx(d[mt][nt][0])
                          + wa1 * tanh_approx(d[mt][nt][1]);
                e[mt][1] += wa0 * tanh_approx(d[mt][nt][2])
                          + wa1 * tanh_approx(d[mt][nt][3]);
            }
        }
        #pragma unroll
        for (int mt = 0; mt < 2; mt++)
            #pragma unroll
            for (int r = 0; r < 2; r++) {
                e[mt][r] += __shfl_xor_sync(0xFFFFFFFFu, e[mt][r], 1);
                e[mt][r] += __shfl_xor_sync(0xFFFFFFFFu, e[mt][r], 2);
            }
        if (t == 0) {
            #pragma unroll
            for (int mt = 0; mt < 2; mt++) {
                int row = wm * 32 + mt * 16 + g;
                sPart[wn * 128 + row]     = e[mt][0];
                sPart[wn * 128 + row + 8] = e[mt][1];
            }
        }
        __syncthreads();
        if (tid < 128)
            g_energy[(size_t)tile * 128 + tid] = sPart[tid] + sPart[128 + tid] + ba;
    }
}

// ---------------------------- Kernel 2: softmax -> alpha --------------------
__global__ void __launch_bounds__(256)
softmax_kernel(const float* __restrict__ accw, const float* __restrict__ beta_ptr,
               float* __restrict__ out) {
    __shared__ float s_e[2048];
    __shared__ float s_red[256];
    int b = blockIdx.x, tid = threadIdx.x;
    const float* aw = accw + (size_t)b * Tlen;
    const float* en = g_energy + (size_t)b * Tlen;

    float lm = -INFINITY;
    for (int t = tid; t < Tlen; t += 256) lm = fmaxf(lm, aw[t]);
    s_red[tid] = lm; __syncthreads();
    for (int s = 128; s > 0; s >>= 1) {
        if (tid < s) s_red[tid] = fmaxf(s_red[tid], s_red[tid + s]);
        __syncthreads();
    }
    float denom = fmaxf(s_red[0], 1e-6f);
    __syncthreads();

    float bet = beta_ptr[0];
    float bp = (bet > 20.f) ? bet : log1pf(expf(bet));

    lm = -INFINITY;
    for (int t = tid; t < Tlen; t += 256) {
        float e = en[t] * (1.f + bp * (aw[t] / denom));
        s_e[t] = e;
        lm = fmaxf(lm, e);
    }
    s_red[tid] = lm; __syncthreads();
    for (int s = 128; s > 0; s >>= 1) {
        if (tid < s) s_red[tid] = fmaxf(s_red[tid], s_red[tid + s]);
        __syncthreads();
    }
    float m = s_red[0];
    __syncthreads();

    float ls = 0.f;
    for (int t = tid; t < Tlen; t += 256) {
        float ex = expf(s_e[t] - m);
        s_e[t] = ex;
        ls += ex;
    }
    s_red[tid] = ls; __syncthreads();
    for (int s = 128; s > 0; s >>= 1) {
        if (tid < s) s_red[tid] += s_red[tid + s];
        __syncthreads();
    }
    float inv = 1.f / s_red[0];
    __syncthreads();

    float* alpha_out = out + Bsz * Hdim + (size_t)b * Tlen;
    for (int t = tid; t < Tlen; t += 256)
        alpha_out[t] = s_e[t] * inv;
}

// -------------------- Kernel 3: context partials (1024 CTAs) ----------------
__global__ void __launch_bounds__(256)
context_partial_kernel(const float* __restrict__ Hp, const float* __restrict__ out) {
    __shared__ float s_a[256];
    __shared__ float s_ctx[8 * 128];
    int b = blockIdx.x >> 3, chunk = blockIdx.x & 7;
    int tid = threadIdx.x, w = tid >> 5, lane = tid & 31;

    const float* alpha = out + Bsz * Hdim + (size_t)b * Tlen + chunk * 256;
    s_a[tid] = alpha[tid];
    __syncthreads();

    const float4* hp = (const float4*)(Hp + ((size_t)b * Tlen + chunk * 256) * Hdim);
    float4 acc = {0.f, 0.f, 0.f, 0.f};
    #pragma unroll 4
    for (int t = w; t < 256; t += 8) {
        float a = s_a[t];
        float4 v = hp[t * 32 + lane];
        acc.x += a * v.x; acc.y += a * v.y; acc.z += a * v.z; acc.w += a * v.w;
    }
    s_ctx[w * 128 + lane * 4 + 0] = acc.x;
    s_ctx[w * 128 + lane * 4 + 1] = acc.y;
    s_ctx[w * 128 + lane * 4 + 2] = acc.z;
    s_ctx[w * 128 + lane * 4 + 3] = acc.w;
    __syncthreads();
    if (tid < 128) {
        float c = 0.f;
        #pragma unroll
        for (int ww = 0; ww < 8; ww++) c += s_ctx[ww * 128 + tid];
        g_ctx_part[(size_t)blockIdx.x * 128 + tid] = c;
    }
}

// -------------------- Kernel 4: reduce 8 partials per batch -----------------
__global__ void __launch_bounds__(128)
context_reduce_kernel(float* __restrict__ out) {
    int b = blockIdx.x, tid = threadIdx.x;
    float c = 0.f;
    #pragma unroll
    for (int k = 0; k < 8; k++)
        c += g_ctx_part[((size_t)b * 8 + k) * 128 + tid];
    out[(size_t)b * Hdim + tid] = c;
}

// ---------------------------- launcher --------------------------------------
extern "C" void kernel_launch(void* const* d_in, const int* in_sizes, int n_in,
                              void* d_out, int out_size) {
    (void)in_sizes; (void)n_in; (void)out_size;
    const float* Hp   = (const float*)d_in[0];
    const float* Hd   = (const float*)d_in[1];
    const float* accw = (const float*)d_in[2];
    const float* Wh   = (const float*)d_in[3];
    const float* Wd   = (const float*)d_in[4];
    const float* Wa   = (const float*)d_in[5];
    const float* ba   = (const float*)d_in[6];
    const float* beta = (const float*)d_in[7];
    float* out = (float*)d_out;

    cudaFuncSetAttribute(energy_kernel, cudaFuncAttributeMaxDynamicSharedMemorySize, SMEM1);
    energy_kernel<<<GRID1, 256, SMEM1>>>(Hp, Hd, Wh, Wd, Wa, ba);
    softmax_kernel<<<Bsz, 256>>>(accw, beta, out);
    context_partial_kernel<<<Bsz * 8, 256>>>(Hp, out);
    context_reduce_kernel<<<Bsz, 128>>>(out);
}

// round 12
// speedup vs baseline: 2.8217x; 1.0194x over previous
#include <cuda_runtime.h>
#include <cuda_bf16.h>
#include <cuda_fp16.h>
#include <cstdint>
#include <math.h>

// ----------------------------------------------------------------------------
// B=128, T=2048, H=128
//   z = tanh(Hp @ Wh^T + Hd @ Wd^T); energy = z @ Wa + ba
//   alpha = softmax_T(energy * (1 + softplus(beta)*acc_w/max(acc_w)))
//   context = sum_t alpha * Hp
// Output: [context (B*H) | alpha (B*T)] fp32
//
// sm_103 (non-'a') ptxas: tcgen05 unavailable -> legacy mma.sync (HMMA).
// Single-term fp16 MMA, fp32 accum. Convert + prefetch fully overlapped with
// MMA via per-thread-partitioned stage buffer (no barriers on stage).
// ----------------------------------------------------------------------------

static constexpr int Bsz = 128, Tlen = 2048, Hdim = 128;
static constexpr int NTILES = Bsz * Tlen / 128;   // 2048 tiles of 128 tokens
static constexpr int GRID1  = 152;                // persistent CTAs (GB300 SMs)

__device__ float g_energy[Bsz * Tlen];
__device__ float g_ctx_part[Bsz * 8 * Hdim];      // context partials

// ---------------------------- helpers ---------------------------------------
__device__ __forceinline__ uint32_t smem_u32(const void* p) {
    uint32_t a;
    asm("{ .reg .u64 t; cvta.to.shared.u64 t, %1; cvt.u32.u64 %0, t; }"
        : "=r"(a) : "l"(p));
    return a;
}

__device__ __forceinline__ void ldsm_x4(uint32_t* r, uint32_t addr) {
    asm volatile("ldmatrix.sync.aligned.m8n8.x4.shared.b16 {%0,%1,%2,%3}, [%4];"
                 : "=r"(r[0]), "=r"(r[1]), "=r"(r[2]), "=r"(r[3]) : "r"(addr));
}

__device__ __forceinline__ void mma16816(float* d, const uint32_t* a,
                                         uint32_t b0, uint32_t b1) {
    asm volatile("mma.sync.aligned.m16n8k16.row.col.f32.f16.f16.f32 "
                 "{%0,%1,%2,%3}, {%4,%5,%6,%7}, {%8,%9}, {%0,%1,%2,%3};"
                 : "+f"(d[0]), "+f"(d[1]), "+f"(d[2]), "+f"(d[3])
                 : "r"(a[0]), "r"(a[1]), "r"(a[2]), "r"(a[3]), "r"(b0), "r"(b1));
}

__device__ __forceinline__ float tanh_approx(float x) {
    float y;
    asm("tanh.approx.f32 %0, %1;" : "=f"(y) : "f"(x));
    return y;
}

__device__ __forceinline__ void cp_async16(uint32_t saddr, const void* g) {
    asm volatile("cp.async.cg.shared.global [%0], [%1], 16;"
                 :: "r"(saddr), "l"(g) : "memory");
}
#define CP_COMMIT() asm volatile("cp.async.commit_group;" ::: "memory")
#define CP_WAIT0()  asm volatile("cp.async.wait_group 0;" ::: "memory")

// ---------------------------- SMEM layout -----------------------------------
// fp16 tiles: 128 rows x 136 halves (pitch 272 B -> 4-bank row rotation,
// conflict-free ldmatrix).
static constexpr int PITCH_B  = 272;
static constexpr int TILE_B   = 128 * PITCH_B;       // 34816 B
static constexpr int SM_AH0   = 0;                   // Hp tile (fp16)
static constexpr int SM_AH1   = SM_AH0 + TILE_B;     // Hd tile (fp16)
static constexpr int SM_WH    = SM_AH1 + TILE_B;     // Wh (fp16)
static constexpr int SM_WD    = SM_WH + TILE_B;      // Wd (fp16)
static constexpr int SM_STAGE = SM_WD + TILE_B;      // raw fp32 128x128 (warp-partitioned)
static constexpr int SM_WA    = SM_STAGE + 65536;    // 204800
static constexpr int SM_PART  = SM_WA + 512;         // 205312: 2x128 fp32
static constexpr int SMEM1    = SM_PART + 1024;      // 206336 B

// Each thread owns 16 float4s of the stage: fi = wid*512 + k*32 + lane, k=0..15.
// The SAME thread cp.asyncs, converts, and re-prefetches those fi -> no barrier
// is ever needed on the stage buffer (per-thread cp.async.wait orders it).

__device__ __forceinline__ void prefetch_own(uint32_t sb, const float* __restrict__ src,
                                             int fbase) {
    #pragma unroll
    for (int k = 0; k < 16; k++) {
        int fi = fbase + k * 32;
        cp_async16(sb + SM_STAGE + (uint32_t)fi * 16, src + (size_t)fi * 4);
    }
    CP_COMMIT();
}

__device__ __forceinline__ void convert_one(char* smem, int dst, int fi,
                                            const float4* stg) {
    float4 v = stg[fi];
    int row = fi >> 5, c = fi & 31;
    __half2 h0 = __floats2half2_rn(v.x, v.y);
    __half2 h1 = __floats2half2_rn(v.z, v.w);
    *(uint2*)(smem + dst + (uint32_t)row * PITCH_B + (uint32_t)c * 8) =
        make_uint2(*(const uint32_t*)&h0, *(const uint32_t*)&h1);
}

// One GEMM pass: D += AH(aBase) @ W(wBase)^T, interleaved with (optional)
// convert of the stage into cvtDst and (optional) prefetch of pf into stage.
template <bool CVT, bool PF>
__device__ __forceinline__ void pass_ic(char* smem, uint32_t sb,
                                        uint32_t aBase, uint32_t wBase, int cvtDst,
                                        const float* __restrict__ pf, int fbase,
                                        int lane, int wm, int wn, float d[2][8][4]) {
    uint32_t arow = (uint32_t)(wm * 32 + (lane & 15));
    uint32_t acol = (uint32_t)((lane >> 4) * 8);
    uint32_t brow = (uint32_t)(wn * 64 + (lane & 7));
    uint32_t bcol = (uint32_t)((lane >> 3) * 8);
    const float4* stg = (const float4*)(smem + SM_STAGE);
    #pragma unroll
    for (int k2 = 0; k2 < 4; k2++) {
        uint32_t k0 = (uint32_t)(k2 * 32);
        uint32_t a[2][2][4];
        #pragma unroll
        for (int mt = 0; mt < 2; mt++)
            #pragma unroll
            for (int ks = 0; ks < 2; ks++)
                ldsm_x4(a[mt][ks],
                        aBase + (arow + mt * 16) * PITCH_B
                              + (k0 + ks * 16 + acol) * 2);
        #pragma unroll
        for (int nt = 0; nt < 8; nt++) {
            uint32_t b[4];
            ldsm_x4(b, wBase + (brow + nt * 8) * PITCH_B + (k0 + bcol) * 2);
            mma16816(d[0][nt], a[0][0], b[0], b[1]);
            mma16816(d[0][nt], a[0][1], b[2], b[3]);
            mma16816(d[1][nt], a[1][0], b[0], b[1]);
            mma16816(d[1][nt], a[1][1], b[2], b[3]);
        }
        if (CVT) {
            if (k2 == 0) CP_WAIT0();    // this thread's staged rows have landed
            #pragma unroll
            for (int j = 0; j < 4; j++)
                convert_one(smem, cvtDst, fbase + (k2 * 4 + j) * 32, stg);
        }
    }
    if (PF) prefetch_own(sb, pf, fbase);
}

__global__ void __launch_bounds__(256, 1)
energy_kernel(const float* __restrict__ Hp, const float* __restrict__ Hd,
              const float* __restrict__ Wh, const float* __restrict__ Wd,
              const float* __restrict__ Wa, const float* __restrict__ ba_ptr) {
    extern __shared__ char smem[];
    uint32_t sb = smem_u32(smem);
    const int tid = threadIdx.x;
    const int wid = tid >> 5, lane = tid & 31;
    const int wm  = wid >> 1, wn = wid & 1;
    const int g   = lane >> 2, t = lane & 3;
    const int fbase = wid * 512 + lane;

    // one-time: weights fp32 -> fp16 tiles
    for (int idx = tid; idx < 8192; idx += 256) {
        int o = idx >> 6, h = (idx & 63) * 2;
        uint32_t off = (uint32_t)o * PITCH_B + (uint32_t)h * 2;
        float2 a = *(const float2*)(Wh + o * 128 + h);
        float2 b = *(const float2*)(Wd + o * 128 + h);
        __half2 ah = __floats2half2_rn(a.x, a.y);
        __half2 bh = __floats2half2_rn(b.x, b.y);
        *(uint32_t*)(smem + SM_WH + off) = *(const uint32_t*)&ah;
        *(uint32_t*)(smem + SM_WD + off) = *(const uint32_t*)&bh;
    }
    if (tid < 128) ((float*)(smem + SM_WA))[tid] = Wa[tid];
    const float ba = ba_ptr[0];
    float* sPart = (float*)(smem + SM_PART);
    const float* sWa = (const float*)(smem + SM_WA);

    // prologue: stage <- Hp[tile0]; convert -> AH0; stage <- Hd[tile0] in flight
    const int tile0 = blockIdx.x;
    {
        const float4* stg = (const float4*)(smem + SM_STAGE);
        prefetch_own(sb, Hp + (size_t)tile0 * 16384, fbase);
        CP_WAIT0();
        #pragma unroll
        for (int k = 0; k < 16; k++)
            convert_one(smem, SM_AH0, fbase + k * 32, stg);
        prefetch_own(sb, Hd + (size_t)tile0 * 16384, fbase);
    }
    __syncthreads();   // weights + AH0 visible to all warps

    for (int tile = tile0; tile < NTILES; tile += GRID1) {
        size_t nbase = (size_t)(tile + GRID1) * 16384;
        const bool hasNext = (tile + GRID1) < NTILES;

        float d[2][8][4];
        #pragma unroll
        for (int mt = 0; mt < 2; mt++)
            #pragma unroll
            for (int nt = 0; nt < 8; nt++)
                #pragma unroll
                for (int j = 0; j < 4; j++) d[mt][nt][j] = 0.f;

        // pass 1: MMA(Hp_i @ Wh) | convert Hd_i -> AH1 | prefetch Hp_{i+1}
        if (hasNext)
            pass_ic<true, true>(smem, sb, sb + SM_AH0, sb + SM_WH, SM_AH1,
                                Hp + nbase, fbase, lane, wm, wn, d);
        else
            pass_ic<true, false>(smem, sb, sb + SM_AH0, sb + SM_WH, SM_AH1,
                                 nullptr, fbase, lane, wm, wn, d);
        __syncthreads();   // AH1 complete before pass 2 reads it

        // pass 2: MMA(Hd_i @ Wd) | convert Hp_{i+1} -> AH0 | prefetch Hd_{i+1}
        if (hasNext)
            pass_ic<true, true>(smem, sb, sb + SM_AH1, sb + SM_WD, SM_AH0,
                                Hd + nbase, fbase, lane, wm, wn, d);
        else
            pass_ic<false, false>(smem, sb, sb + SM_AH1, sb + SM_WD, SM_AH0,
                                  nullptr, fbase, lane, wm, wn, d);

        // epilogue: energy[token] = ba + sum_o Wa[o]*tanh(D[token][o])
        float e[2][2] = {{0.f, 0.f}, {0.f, 0.f}};
        #pragma unroll
        for (int nt = 0; nt < 8; nt++) {
            int n = wn * 64 + nt * 8 + 2 * t;
            float wa0 = sWa[n], wa1 = sWa[n + 1];
            #pragma unroll
            for (int mt = 0; mt < 2; mt++) {
                e[mt][0] += wa0 * tanh_approx(d[mt][nt][0])
                          + wa1 * tanh_approx(d[mt][nt][1]);
                e[mt][1] += wa0 * tanh_approx(d[mt][nt][2])
                          + wa1 * tanh_approx(d[mt][nt][3]);
            }
        }
        #pragma unroll
        for (int mt = 0; mt < 2; mt++)
            #pragma unroll
            for (int r = 0; r < 2; r++) {
                e[mt][r] += __shfl_xor_sync(0xFFFFFFFFu, e[mt][r], 1);
                e[mt][r] += __shfl_xor_sync(0xFFFFFFFFu, e[mt][r], 2);
            }
        if (t == 0) {
            #pragma unroll
            for (int mt = 0; mt < 2; mt++) {
                int row = wm * 32 + mt * 16 + g;
                sPart[wn * 128 + row]     = e[mt][0];
                sPart[wn * 128 + row + 8] = e[mt][1];
            }
        }
        __syncthreads();   // sPart ready; also AH0 (next Hp) visible for pass 1
        if (tid < 128)
            g_energy[(size_t)tile * 128 + tid] = sPart[tid] + sPart[128 + tid] + ba;
        __syncthreads();   // sPart free before next tile's epilogue reuse
    }
}

// ---------------------------- Kernel 2: softmax -> alpha --------------------
__global__ void __launch_bounds__(256)
softmax_kernel(const float* __restrict__ accw, const float* __restrict__ beta_ptr,
               float* __restrict__ out) {
    __shared__ float s_e[2048];
    __shared__ float s_red[256];
    int b = blockIdx.x, tid = threadIdx.x;
    const float* aw = accw + (size_t)b * Tlen;
    const float* en = g_energy + (size_t)b * Tlen;

    float lm = -INFINITY;
    for (int t = tid; t < Tlen; t += 256) lm = fmaxf(lm, aw[t]);
    s_red[tid] = lm; __syncthreads();
    for (int s = 128; s > 0; s >>= 1) {
        if (tid < s) s_red[tid] = fmaxf(s_red[tid], s_red[tid + s]);
        __syncthreads();
    }
    float denom = fmaxf(s_red[0], 1e-6f);
    __syncthreads();

    float bet = beta_ptr[0];
    float bp = (bet > 20.f) ? bet : log1pf(expf(bet));

    lm = -INFINITY;
    for (int t = tid; t < Tlen; t += 256) {
        float e = en[t] * (1.f + bp * (aw[t] / denom));
        s_e[t] = e;
        lm = fmaxf(lm, e);
    }
    s_red[tid] = lm; __syncthreads();
    for (int s = 128; s > 0; s >>= 1) {
        if (tid < s) s_red[tid] = fmaxf(s_red[tid], s_red[tid + s]);
        __syncthreads();
    }
    float m = s_red[0];
    __syncthreads();

    float ls = 0.f;
    for (int t = tid; t < Tlen; t += 256) {
        float ex = expf(s_e[t] - m);
        s_e[t] = ex;
        ls += ex;
    }
    s_red[tid] = ls; __syncthreads();
    for (int s = 128; s > 0; s >>= 1) {
        if (tid < s) s_red[tid] += s_red[tid + s];
        __syncthreads();
    }
    float inv = 1.f / s_red[0];
    __syncthreads();

    float* alpha_out = out + Bsz * Hdim + (size_t)b * Tlen;
    for (int t = tid; t < Tlen; t += 256)
        alpha_out[t] = s_e[t] * inv;
}

// -------------------- Kernel 3: context partials (1024 CTAs) ----------------
__global__ void __launch_bounds__(256)
context_partial_kernel(const float* __restrict__ Hp, const float* __restrict__ out) {
    __shared__ float s_a[256];
    __shared__ float s_ctx[8 * 128];
    int b = blockIdx.x >> 3, chunk = blockIdx.x & 7;
    int tid = threadIdx.x, w = tid >> 5, lane = tid & 31;

    const float* alpha = out + Bsz * Hdim + (size_t)b * Tlen + chunk * 256;
    s_a[tid] = alpha[tid];
    __syncthreads();

    const float4* hp = (const float4*)(Hp + ((size_t)b * Tlen + chunk * 256) * Hdim);
    float4 acc = {0.f, 0.f, 0.f, 0.f};
    #pragma unroll 4
    for (int t = w; t < 256; t += 8) {
        float a = s_a[t];
        float4 v = hp[t * 32 + lane];
        acc.x += a * v.x; acc.y += a * v.y; acc.z += a * v.z; acc.w += a * v.w;
    }
    s_ctx[w * 128 + lane * 4 + 0] = acc.x;
    s_ctx[w * 128 + lane * 4 + 1] = acc.y;
    s_ctx[w * 128 + lane * 4 + 2] = acc.z;
    s_ctx[w * 128 + lane * 4 + 3] = acc.w;
    __syncthreads();
    if (tid < 128) {
        float c = 0.f;
        #pragma unroll
        for (int ww = 0; ww < 8; ww++) c += s_ctx[ww * 128 + tid];
        g_ctx_part[(size_t)blockIdx.x * 128 + tid] = c;
    }
}

// -------------------- Kernel 4: reduce 8 partials per batch -----------------
__global__ void __launch_bounds__(128)
context_reduce_kernel(float* __restrict__ out) {
    int b = blockIdx.x, tid = threadIdx.x;
    float c = 0.f;
    #pragma unroll
    for (int k = 0; k < 8; k++)
        c += g_ctx_part[((size_t)b * 8 + k) * 128 + tid];
    out[(size_t)b * Hdim + tid] = c;
}

// ---------------------------- launcher --------------------------------------
extern "C" void kernel_launch(void* const* d_in, const int* in_sizes, int n_in,
                              void* d_out, int out_size) {
    (void)in_sizes; (void)n_in; (void)out_size;
    const float* Hp   = (const float*)d_in[0];
    const float* Hd   = (const float*)d_in[1];
    const float* accw = (const float*)d_in[2];
    const float* Wh   = (const float*)d_in[3];
    const float* Wd   = (const float*)d_in[4];
    const float* Wa   = (const float*)d_in[5];
    const float* ba   = (const float*)d_in[6];
    const float* beta = (const float*)d_in[7];
    float* out = (float*)d_out;

    cudaFuncSetAttribute(energy_kernel, cudaFuncAttributeMaxDynamicSharedMemorySize, SMEM1);
    energy_kernel<<<GRID1, 256, SMEM1>>>(Hp, Hd, Wh, Wd, Wa, ba);
    softmax_kernel<<<Bsz, 256>>>(accw, beta, out);
    context_partial_kernel<<<Bsz * 8, 256>>>(Hp, out);
    context_reduce_kernel<<<Bsz, 128>>>(out);
}